// round 15
// baseline (speedup 1.0000x reference)
#include <cuda_runtime.h>

#define NB 16
#define NH 16
#define NI 512
#define NE 512
#define IE (NI * NE)
#define JSPLIT 4

// emb partials (device scratch; allocations forbidden)
__device__ float g_embp[JSPLIT][NB * NH * NE];  // 2 MB

// ---- packed fp32x2 helpers -------------------------------------------------
__device__ __forceinline__ void fma2(unsigned long long& d,
                                     unsigned long long a, unsigned long long b) {
    asm("fma.rn.f32x2 %0, %1, %2, %0;" : "+l"(d) : "l"(a), "l"(b));
}

// ---- tf32 helpers ----------------------------------------------------------
__device__ __forceinline__ unsigned f2tf32(float f) {
    unsigned u;
    asm("cvt.rna.tf32.f32 %0, %1;" : "=r"(u) : "f"(f));
    return u;
}
__device__ __forceinline__ void tf32_split(float f, unsigned& hi, unsigned& lo) {
    hi = f2tf32(f);
    lo = f2tf32(f - __uint_as_float(hi));
}
__device__ __forceinline__ void mma_tf32(float c[4], const unsigned a[4], const unsigned b[2]) {
    asm("mma.sync.aligned.m16n8k8.row.col.f32.tf32.tf32.f32 "
        "{%0,%1,%2,%3}, {%4,%5,%6,%7}, {%8,%9}, {%0,%1,%2,%3};"
        : "+f"(c[0]), "+f"(c[1]), "+f"(c[2]), "+f"(c[3])
        : "r"(a[0]), "r"(a[1]), "r"(a[2]), "r"(a[3]), "r"(b[0]), "r"(b[1]));
}

// ---------------------------------------------------------------------------
// Kernel 1 (R14 winner, verbatim): emb partials + bias-init of out.
// Thread tile 8b x 8h x 2e: LDG.64 operands + fma.rn.f32x2 accumulators.
// ---------------------------------------------------------------------------
__global__ __launch_bounds__(256, 2) void emb_kernel(const float* __restrict__ x,
                                                     const float* __restrict__ wv,
                                                     const float* __restrict__ bias,
                                                     float* __restrict__ out) {
    const int t   = threadIdx.x;
    const int bid = blockIdx.x;        // 256 blocks

    // Bias init of the output (gemm accumulates on top).
    {
        const int oidx = bid * 256 + t;            // 0 .. 65535
        const float bv = bias[oidx & (NE - 1)];
        out[oidx]         = bv;
        out[oidx + 65536] = bv;
    }

    const int el  = t & 15;            // e pair lane
    const int bq  = (t >> 4) & 1;      // b quad select
    const int sl  = t >> 5;            // j slice (warp id) 0..7
    const int ec  = bid & 15;          // e chunk 0..15
    const int hg  = (bid >> 4) & 1;    // h half
    const int bg  = (bid >> 5) & 1;    // b half
    const int js  = bid >> 6;          // j split 0..3

    const int e0 = ec * 32 + el * 2;   // 8-byte aligned
    const float* xp = x  + (bg * 8 + bq * 4) * IE + e0;
    const float* wp = wv + hg * 8 * IE + e0;

    unsigned long long acc[4][8];      // packed float2 accumulators
#pragma unroll
    for (int i = 0; i < 4; ++i)
#pragma unroll
        for (int k = 0; k < 8; ++k) acc[i][k] = 0ull;

    const int j0 = js * 128;
#pragma unroll 2
    for (int jj = 0; jj < 16; ++jj) {
        const int joff = (j0 + sl + jj * 8) * NE;
        unsigned long long xv[4], wv8[8];
#pragma unroll
        for (int i = 0; i < 4; ++i)
            xv[i]  = *(const unsigned long long*)(xp + i * IE + joff);
#pragma unroll
        for (int k = 0; k < 8; ++k)
            wv8[k] = *(const unsigned long long*)(wp + k * IE + joff);
#pragma unroll
        for (int i = 0; i < 4; ++i)
#pragma unroll
            for (int k = 0; k < 8; ++k)
                fma2(acc[i][k], xv[i], wv8[k]);
    }

    // Reduce the 8 j-slices: two 16-ik halves through 32KB of float2 smem.
    __shared__ unsigned long long red[8][16][32];  // [slice][ik][lane]
    const int lane = t & 31;           // el | bq<<4
#pragma unroll
    for (int half = 0; half < 2; ++half) {
        __syncthreads();
#pragma unroll
        for (int ik = 0; ik < 16; ++ik) {
            const int ikf = half * 16 + ik;        // i*8 + k
            red[sl][ik][lane] = acc[ikf >> 3][ikf & 7];
        }
        __syncthreads();
#pragma unroll
        for (int r = 0; r < 2; ++r) {
            const int item = t + r * 256;          // 0..511
            const int ik   = item >> 5;            // 0..15
            const int ln   = item & 31;
            float2 s = make_float2(0.f, 0.f);
#pragma unroll
            for (int q = 0; q < 8; ++q) {
                const float2 v = *(const float2*)&red[q][ik][ln];
                s.x += v.x; s.y += v.y;
            }
            const int ikf = half * 16 + ik;
            const int b = bg * 8 + ((ln >> 4) & 1) * 4 + (ikf >> 3);
            const int h = hg * 8 + (ikf & 7);
            const int e = ec * 32 + (ln & 15) * 2;
            *(float2*)&g_embp[js][(b * NH + h) * NE + e] = s;
        }
    }
}

// ---------------------------------------------------------------------------
// Kernel 2 (PDL + tf32 MMA, split HOISTED to staging):
// out[m][n] += sum_k emb[m][k]*w[n][k]  (bias already in out)
// M=256,N=512,K=512. Tiles 64m x 64n x 32k, split-K=16 -> grid 512.
// Staging converts each element to (hi,lo) tf32 ONCE and stores both planes
// in smem (35 KB); the mainloop is pure LDS + MMA (no cvt: was 12.7% alu,
// the issue-dominant term in R13/R14). B planes staged pre-PDL-gate.
// ---------------------------------------------------------------------------
__global__ __launch_bounds__(256) void gemm_kernel(const float* __restrict__ w,
                                                   float* __restrict__ out) {
    const int t   = threadIdx.x;
    const int bid = blockIdx.x;        // 512 = 4 mt x 8 nt x 16 kt
    const int kt  = bid & 15;
    const int nt  = (bid >> 4) & 7;
    const int mt  = bid >> 7;
    const int m0 = mt * 64, n0 = nt * 64, k0 = kt * 32;

    __shared__ unsigned sah[32][68], sal[32][68];  // A hi/lo [k][m]
    __shared__ unsigned sbh[32][68], sbl[32][68];  // B hi/lo [k][n]

    // ---- B planes first: independent of emb (overlaps its tail via PDL) ---
#pragma unroll
    for (int r = 0; r < 2; ++r) {
        const int lin = t + r * 256;        // 512 float4 slots
        const int row = lin >> 3;           // n 0..63
        const int kq  = (lin & 7) * 4;      // 0..28
        const float4 b4 = *(const float4*)&w[(n0 + row) * NE + k0 + kq];
        const float bf[4] = {b4.x, b4.y, b4.z, b4.w};
#pragma unroll
        for (int q = 0; q < 4; ++q)
            tf32_split(bf[q], sbh[kq + q][row], sbl[kq + q][row]);
    }

    cudaGridDependencySynchronize();

    // ---- A planes: 64m x 32k, folded over the 4 j-split partials ----------
#pragma unroll
    for (int r = 0; r < 2; ++r) {
        const int lin = t + r * 256;
        const int row = lin >> 3;           // m 0..63
        const int kq  = (lin & 7) * 4;
        const int aoff = (m0 + row) * NE + k0 + kq;
        float4 a = *(const float4*)&g_embp[0][aoff];
#pragma unroll
        for (int p = 1; p < JSPLIT; ++p) {
            const float4 v = *(const float4*)&g_embp[p][aoff];
            a.x += v.x; a.y += v.y; a.z += v.z; a.w += v.w;
        }
        const float af[4] = {a.x, a.y, a.z, a.w};
#pragma unroll
        for (int q = 0; q < 4; ++q)
            tf32_split(af[q], sah[kq + q][row], sal[kq + q][row]);
    }
    __syncthreads();

    const int wid  = t >> 5;
    const int lane = t & 31;
    const int gid  = lane >> 2;        // group id 0..7
    const int tig  = lane & 3;         // thread in group 0..3
    const int mw = (wid & 3) * 16;     // warp m-offset in tile
    const int nw = (wid >> 2) * 32;    // warp n-offset in tile

    float c[4][4];                     // [ntile][creg]
#pragma unroll
    for (int i = 0; i < 4; ++i)
#pragma unroll
        for (int j = 0; j < 4; ++j) c[i][j] = 0.f;

#pragma unroll
    for (int ks = 0; ks < 4; ++ks) {   // 4 mma k-steps of 8
        const int kb = ks * 8;
        // A fragments straight from the hi/lo planes (no cvt)
        unsigned ah[4], al[4];
        ah[0] = sah[kb + tig    ][mw + gid    ];  al[0] = sal[kb + tig    ][mw + gid    ];
        ah[1] = sah[kb + tig    ][mw + gid + 8];  al[1] = sal[kb + tig    ][mw + gid + 8];
        ah[2] = sah[kb + tig + 4][mw + gid    ];  al[2] = sal[kb + tig + 4][mw + gid    ];
        ah[3] = sah[kb + tig + 4][mw + gid + 8];  al[3] = sal[kb + tig + 4][mw + gid + 8];
#pragma unroll
        for (int ntile = 0; ntile < 4; ++ntile) {
            unsigned bh[2], bl[2];
            bh[0] = sbh[kb + tig    ][nw + ntile * 8 + gid];
            bl[0] = sbl[kb + tig    ][nw + ntile * 8 + gid];
            bh[1] = sbh[kb + tig + 4][nw + ntile * 8 + gid];
            bl[1] = sbl[kb + tig + 4][nw + ntile * 8 + gid];
            mma_tf32(c[ntile], ah, bh);   // hi*hi
            mma_tf32(c[ntile], al, bh);   // lo*hi
            mma_tf32(c[ntile], ah, bl);   // hi*lo
        }
    }

    // Epilogue: c0:(gid,2tig) c1:(gid,2tig+1) c2:(gid+8,2tig) c3:(gid+8,2tig+1)
    const int gm = m0 + mw + gid;
    const int gn = n0 + nw + tig * 2;
#pragma unroll
    for (int ntile = 0; ntile < 4; ++ntile) {
        float* op = &out[gm * NE + gn + ntile * 8];
        atomicAdd(op + 0,          c[ntile][0]);
        atomicAdd(op + 1,          c[ntile][1]);
        atomicAdd(op + 8 * NE + 0, c[ntile][2]);
        atomicAdd(op + 8 * NE + 1, c[ntile][3]);
    }
}

extern "C" void kernel_launch(void* const* d_in, const int* in_sizes, int n_in,
                              void* d_out, int out_size) {
    const float* x    = (const float*)d_in[0];  // [16,1,512,512]
    // d_in[1] = W_q, d_in[2] = W_k: mathematically dead (softmax cols sum to 1)
    const float* wv   = (const float*)d_in[3];  // [1,16,512,512]
    const float* mlpw = (const float*)d_in[4];  // [512,512]
    const float* mlpb = (const float*)d_in[5];  // [512]
    float* out = (float*)d_out;                 // [16,16,512]

    emb_kernel<<<256, 256>>>(x, wv, mlpb, out);

    cudaLaunchConfig_t cfg = {};
    cfg.gridDim  = dim3(512, 1, 1);
    cfg.blockDim = dim3(256, 1, 1);
    cfg.dynamicSmemBytes = 0;
    cudaLaunchAttribute attrs[1];
    attrs[0].id = cudaLaunchAttributeProgrammaticStreamSerialization;
    attrs[0].val.programmaticStreamSerializationAllowed = 1;
    cfg.attrs = attrs;
    cfg.numAttrs = 1;
    cudaLaunchKernelEx(&cfg, gemm_kernel, mlpw, (float*)d_out);
}

// round 16
// speedup vs baseline: 1.1067x; 1.1067x over previous
#include <cuda_runtime.h>

#define NB 16
#define NH 16
#define NI 512
#define NE 512
#define IE (NI * NE)
#define JSPLIT 4

// emb partials (device scratch; allocations forbidden)
__device__ float g_embp[JSPLIT][NB * NH * NE];  // 2 MB

// ---- packed fp32x2 helpers -------------------------------------------------
__device__ __forceinline__ void fma2(unsigned long long& d,
                                     unsigned long long a, unsigned long long b) {
    asm("fma.rn.f32x2 %0, %1, %2, %0;" : "+l"(d) : "l"(a), "l"(b));
}

// ---- tf32 helpers ----------------------------------------------------------
__device__ __forceinline__ unsigned f2tf32(float f) {
    unsigned u;
    asm("cvt.rna.tf32.f32 %0, %1;" : "=r"(u) : "f"(f));
    return u;
}
__device__ __forceinline__ uint2 tf32_split2(float f) {
    uint2 r;
    r.x = f2tf32(f);
    r.y = f2tf32(f - __uint_as_float(r.x));
    return r;
}
__device__ __forceinline__ void mma_tf32(float c[4], const unsigned a[4], const unsigned b[2]) {
    asm("mma.sync.aligned.m16n8k8.row.col.f32.tf32.tf32.f32 "
        "{%0,%1,%2,%3}, {%4,%5,%6,%7}, {%8,%9}, {%0,%1,%2,%3};"
        : "+f"(c[0]), "+f"(c[1]), "+f"(c[2]), "+f"(c[3])
        : "r"(a[0]), "r"(a[1]), "r"(a[2]), "r"(a[3]), "r"(b[0]), "r"(b[1]));
}

// ---------------------------------------------------------------------------
// Kernel 1 (R14 winner, verbatim): emb partials + bias-init of out.
// Thread tile 8b x 8h x 2e: LDG.64 operands + fma.rn.f32x2 accumulators.
// ---------------------------------------------------------------------------
__global__ __launch_bounds__(256, 2) void emb_kernel(const float* __restrict__ x,
                                                     const float* __restrict__ wv,
                                                     const float* __restrict__ bias,
                                                     float* __restrict__ out) {
    const int t   = threadIdx.x;
    const int bid = blockIdx.x;        // 256 blocks

    // Bias init of the output (gemm accumulates on top).
    {
        const int oidx = bid * 256 + t;            // 0 .. 65535
        const float bv = bias[oidx & (NE - 1)];
        out[oidx]         = bv;
        out[oidx + 65536] = bv;
    }

    const int el  = t & 15;            // e pair lane
    const int bq  = (t >> 4) & 1;      // b quad select
    const int sl  = t >> 5;            // j slice (warp id) 0..7
    const int ec  = bid & 15;          // e chunk 0..15
    const int hg  = (bid >> 4) & 1;    // h half
    const int bg  = (bid >> 5) & 1;    // b half
    const int js  = bid >> 6;          // j split 0..3

    const int e0 = ec * 32 + el * 2;   // 8-byte aligned
    const float* xp = x  + (bg * 8 + bq * 4) * IE + e0;
    const float* wp = wv + hg * 8 * IE + e0;

    unsigned long long acc[4][8];      // packed float2 accumulators
#pragma unroll
    for (int i = 0; i < 4; ++i)
#pragma unroll
        for (int k = 0; k < 8; ++k) acc[i][k] = 0ull;

    const int j0 = js * 128;
#pragma unroll 2
    for (int jj = 0; jj < 16; ++jj) {
        const int joff = (j0 + sl + jj * 8) * NE;
        unsigned long long xv[4], wv8[8];
#pragma unroll
        for (int i = 0; i < 4; ++i)
            xv[i]  = *(const unsigned long long*)(xp + i * IE + joff);
#pragma unroll
        for (int k = 0; k < 8; ++k)
            wv8[k] = *(const unsigned long long*)(wp + k * IE + joff);
#pragma unroll
        for (int i = 0; i < 4; ++i)
#pragma unroll
            for (int k = 0; k < 8; ++k)
                fma2(acc[i][k], xv[i], wv8[k]);
    }

    // Reduce the 8 j-slices: two 16-ik halves through 32KB of float2 smem.
    __shared__ unsigned long long red[8][16][32];  // [slice][ik][lane]
    const int lane = t & 31;           // el | bq<<4
#pragma unroll
    for (int half = 0; half < 2; ++half) {
        __syncthreads();
#pragma unroll
        for (int ik = 0; ik < 16; ++ik) {
            const int ikf = half * 16 + ik;        // i*8 + k
            red[sl][ik][lane] = acc[ikf >> 3][ikf & 7];
        }
        __syncthreads();
#pragma unroll
        for (int r = 0; r < 2; ++r) {
            const int item = t + r * 256;          // 0..511
            const int ik   = item >> 5;            // 0..15
            const int ln   = item & 31;
            float2 s = make_float2(0.f, 0.f);
#pragma unroll
            for (int q = 0; q < 8; ++q) {
                const float2 v = *(const float2*)&red[q][ik][ln];
                s.x += v.x; s.y += v.y;
            }
            const int ikf = half * 16 + ik;
            const int b = bg * 8 + ((ln >> 4) & 1) * 4 + (ikf >> 3);
            const int h = hg * 8 + (ikf & 7);
            const int e = ec * 32 + (ln & 15) * 2;
            *(float2*)&g_embp[js][(b * NH + h) * NE + e] = s;
        }
    }
}

// ---------------------------------------------------------------------------
// Kernel 2 (PDL + tf32 MMA, hoisted split @ K=64, dynamic smem):
// out[m][n] += sum_k emb[m][k]*w[n][k]  (bias already in out)
// M=256,N=512,K=512. Tiles 64m x 64n x 64k, split-K=8 -> grid 256 (the
// R13/R14 geometry that measured best; R15's K=32 halving was the mistake).
// hi/lo tf32 packed as uint2 in ROW-MAJOR smem [row][k] pad 68: fragment
// LDS.64 conflict-free (row stride 136 words = 8 mod 32 -> banks 8*gid+2*tig
// distinct per phase); staging keeps coalesced global float4 loads.
// Mainloop: 12 LDS.64 + 12 MMA per thread per ks -- no cvt (hoisted).
// ---------------------------------------------------------------------------
__global__ __launch_bounds__(256) void gemm_kernel(const float* __restrict__ w,
                                                   float* __restrict__ out) {
    const int t   = threadIdx.x;
    const int bid = blockIdx.x;        // 256 = 4 mt x 8 nt x 8 kt
    const int kt  = bid & 7;
    const int nt  = (bid >> 3) & 7;
    const int mt  = bid >> 6;
    const int m0 = mt * 64, n0 = nt * 64, k0 = kt * 64;

    extern __shared__ uint2 dsm[];     // 2 x 64 x 68 uint2 = 69632 B
    uint2 (*sa)[68] = (uint2(*)[68])dsm;             // A: [m][k] {hi,lo}
    uint2 (*sb)[68] = (uint2(*)[68])(dsm + 64 * 68); // B: [n][k] {hi,lo}

    // ---- B planes first: independent of emb (overlaps its tail via PDL) ---
#pragma unroll
    for (int r = 0; r < 4; ++r) {
        const int lin = t + r * 256;        // 1024 float4 slots
        const int row = lin >> 4;           // n 0..63
        const int kq  = (lin & 15) * 4;     // 0..60
        const float4 b4 = *(const float4*)&w[(n0 + row) * NE + k0 + kq];
        sb[row][kq + 0] = tf32_split2(b4.x);
        sb[row][kq + 1] = tf32_split2(b4.y);
        sb[row][kq + 2] = tf32_split2(b4.z);
        sb[row][kq + 3] = tf32_split2(b4.w);
    }

    cudaGridDependencySynchronize();

    // ---- A planes: 64m x 64k, folded over the 4 j-split partials ----------
#pragma unroll
    for (int r = 0; r < 4; ++r) {
        const int lin = t + r * 256;
        const int row = lin >> 4;           // m 0..63
        const int kq  = (lin & 15) * 4;
        const int aoff = (m0 + row) * NE + k0 + kq;
        float4 a = *(const float4*)&g_embp[0][aoff];
#pragma unroll
        for (int p = 1; p < JSPLIT; ++p) {
            const float4 v = *(const float4*)&g_embp[p][aoff];
            a.x += v.x; a.y += v.y; a.z += v.z; a.w += v.w;
        }
        sa[row][kq + 0] = tf32_split2(a.x);
        sa[row][kq + 1] = tf32_split2(a.y);
        sa[row][kq + 2] = tf32_split2(a.z);
        sa[row][kq + 3] = tf32_split2(a.w);
    }
    __syncthreads();

    const int wid  = t >> 5;
    const int lane = t & 31;
    const int gid  = lane >> 2;        // group id 0..7
    const int tig  = lane & 3;         // thread in group 0..3
    const int mw = (wid & 3) * 16;     // warp m-offset in tile
    const int nw = (wid >> 2) * 32;    // warp n-offset in tile

    float c[4][4];                     // [ntile][creg]
#pragma unroll
    for (int i = 0; i < 4; ++i)
#pragma unroll
        for (int j = 0; j < 4; ++j) c[i][j] = 0.f;

#pragma unroll
    for (int ks = 0; ks < 8; ++ks) {   // 8 mma k-steps of 8
        const int kb = ks * 8;
        // A fragments: one LDS.64 per element fetches {hi,lo}
        const uint2 a0 = sa[mw + gid    ][kb + tig    ];
        const uint2 a1 = sa[mw + gid + 8][kb + tig    ];
        const uint2 a2 = sa[mw + gid    ][kb + tig + 4];
        const uint2 a3 = sa[mw + gid + 8][kb + tig + 4];
        const unsigned ah[4] = {a0.x, a1.x, a2.x, a3.x};
        const unsigned al[4] = {a0.y, a1.y, a2.y, a3.y};
#pragma unroll
        for (int ntile = 0; ntile < 4; ++ntile) {
            const uint2 b0 = sb[nw + ntile * 8 + gid][kb + tig    ];
            const uint2 b1 = sb[nw + ntile * 8 + gid][kb + tig + 4];
            const unsigned bh[2] = {b0.x, b1.x};
            const unsigned bl[2] = {b0.y, b1.y};
            mma_tf32(c[ntile], ah, bh);   // hi*hi
            mma_tf32(c[ntile], al, bh);   // lo*hi
            mma_tf32(c[ntile], ah, bl);   // hi*lo
        }
    }

    // Epilogue: c0:(gid,2tig) c1:(gid,2tig+1) c2:(gid+8,2tig) c3:(gid+8,2tig+1)
    const int gm = m0 + mw + gid;
    const int gn = n0 + nw + tig * 2;
#pragma unroll
    for (int ntile = 0; ntile < 4; ++ntile) {
        float* op = &out[gm * NE + gn + ntile * 8];
        atomicAdd(op + 0,          c[ntile][0]);
        atomicAdd(op + 1,          c[ntile][1]);
        atomicAdd(op + 8 * NE + 0, c[ntile][2]);
        atomicAdd(op + 8 * NE + 1, c[ntile][3]);
    }
}

extern "C" void kernel_launch(void* const* d_in, const int* in_sizes, int n_in,
                              void* d_out, int out_size) {
    const float* x    = (const float*)d_in[0];  // [16,1,512,512]
    // d_in[1] = W_q, d_in[2] = W_k: mathematically dead (softmax cols sum to 1)
    const float* wv   = (const float*)d_in[3];  // [1,16,512,512]
    const float* mlpw = (const float*)d_in[4];  // [512,512]
    const float* mlpb = (const float*)d_in[5];  // [512]
    float* out = (float*)d_out;                 // [16,16,512]

    const int smem_bytes = 2 * 64 * 68 * (int)sizeof(uint2);  // 69632
    static int attr_set = 0;
    if (!attr_set) {   // idempotent host-side attribute (not a stream op)
        cudaFuncSetAttribute(gemm_kernel,
                             cudaFuncAttributeMaxDynamicSharedMemorySize, smem_bytes);
        attr_set = 1;
    }

    emb_kernel<<<256, 256>>>(x, wv, mlpb, out);

    cudaLaunchConfig_t cfg = {};
    cfg.gridDim  = dim3(256, 1, 1);
    cfg.blockDim = dim3(256, 1, 1);
    cfg.dynamicSmemBytes = smem_bytes;
    cudaLaunchAttribute attrs[1];
    attrs[0].id = cudaLaunchAttributeProgrammaticStreamSerialization;
    attrs[0].val.programmaticStreamSerializationAllowed = 1;
    cfg.attrs = attrs;
    cfg.numAttrs = 1;
    cudaLaunchKernelEx(&cfg, gemm_kernel, mlpw, (float*)d_out);
}

// round 17
// speedup vs baseline: 1.1254x; 1.0169x over previous
#include <cuda_runtime.h>

#define NB 16
#define NH 16
#define NI 512
#define NE 512
#define IE (NI * NE)
#define JSPLIT 4

// emb partials (device scratch; allocations forbidden)
__device__ float g_embp[JSPLIT][NB * NH * NE];  // 2 MB

// ---- packed fp32x2 helpers -------------------------------------------------
__device__ __forceinline__ void fma2(unsigned long long& d,
                                     unsigned long long a, unsigned long long b) {
    asm("fma.rn.f32x2 %0, %1, %2, %0;" : "+l"(d) : "l"(a), "l"(b));
}

// ---- tf32 helpers ----------------------------------------------------------
__device__ __forceinline__ unsigned f2tf32(float f) {
    unsigned u;
    asm("cvt.rna.tf32.f32 %0, %1;" : "=r"(u) : "f"(f));
    return u;
}
__device__ __forceinline__ uint2 tf32_split2(float f) {
    uint2 r;
    r.x = f2tf32(f);
    r.y = f2tf32(f - __uint_as_float(r.x));
    return r;
}
__device__ __forceinline__ void mma_tf32(float c[4], const unsigned a[4], const unsigned b[2]) {
    asm("mma.sync.aligned.m16n8k8.row.col.f32.tf32.tf32.f32 "
        "{%0,%1,%2,%3}, {%4,%5,%6,%7}, {%8,%9}, {%0,%1,%2,%3};"
        : "+f"(c[0]), "+f"(c[1]), "+f"(c[2]), "+f"(c[3])
        : "r"(a[0]), "r"(a[1]), "r"(a[2]), "r"(a[3]), "r"(b[0]), "r"(b[1]));
}

// ---------------------------------------------------------------------------
// Kernel 1 (R14 winner, verbatim): emb partials + bias-init of out.
// Thread tile 8b x 8h x 2e: LDG.64 operands + fma.rn.f32x2 accumulators.
// ---------------------------------------------------------------------------
__global__ __launch_bounds__(256, 2) void emb_kernel(const float* __restrict__ x,
                                                     const float* __restrict__ wv,
                                                     const float* __restrict__ bias,
                                                     float* __restrict__ out) {
    const int t   = threadIdx.x;
    const int bid = blockIdx.x;        // 256 blocks

    // Bias init of the output (gemm accumulates on top).
    {
        const int oidx = bid * 256 + t;            // 0 .. 65535
        const float bv = bias[oidx & (NE - 1)];
        out[oidx]         = bv;
        out[oidx + 65536] = bv;
    }

    const int el  = t & 15;            // e pair lane
    const int bq  = (t >> 4) & 1;      // b quad select
    const int sl  = t >> 5;            // j slice (warp id) 0..7
    const int ec  = bid & 15;          // e chunk 0..15
    const int hg  = (bid >> 4) & 1;    // h half
    const int bg  = (bid >> 5) & 1;    // b half
    const int js  = bid >> 6;          // j split 0..3

    const int e0 = ec * 32 + el * 2;   // 8-byte aligned
    const float* xp = x  + (bg * 8 + bq * 4) * IE + e0;
    const float* wp = wv + hg * 8 * IE + e0;

    unsigned long long acc[4][8];      // packed float2 accumulators
#pragma unroll
    for (int i = 0; i < 4; ++i)
#pragma unroll
        for (int k = 0; k < 8; ++k) acc[i][k] = 0ull;

    const int j0 = js * 128;
#pragma unroll 2
    for (int jj = 0; jj < 16; ++jj) {
        const int joff = (j0 + sl + jj * 8) * NE;
        unsigned long long xv[4], wv8[8];
#pragma unroll
        for (int i = 0; i < 4; ++i)
            xv[i]  = *(const unsigned long long*)(xp + i * IE + joff);
#pragma unroll
        for (int k = 0; k < 8; ++k)
            wv8[k] = *(const unsigned long long*)(wp + k * IE + joff);
#pragma unroll
        for (int i = 0; i < 4; ++i)
#pragma unroll
            for (int k = 0; k < 8; ++k)
                fma2(acc[i][k], xv[i], wv8[k]);
    }

    // Reduce the 8 j-slices: two 16-ik halves through 32KB of float2 smem.
    __shared__ unsigned long long red[8][16][32];  // [slice][ik][lane]
    const int lane = t & 31;           // el | bq<<4
#pragma unroll
    for (int half = 0; half < 2; ++half) {
        __syncthreads();
#pragma unroll
        for (int ik = 0; ik < 16; ++ik) {
            const int ikf = half * 16 + ik;        // i*8 + k
            red[sl][ik][lane] = acc[ikf >> 3][ikf & 7];
        }
        __syncthreads();
#pragma unroll
        for (int r = 0; r < 2; ++r) {
            const int item = t + r * 256;          // 0..511
            const int ik   = item >> 5;            // 0..15
            const int ln   = item & 31;
            float2 s = make_float2(0.f, 0.f);
#pragma unroll
            for (int q = 0; q < 8; ++q) {
                const float2 v = *(const float2*)&red[q][ik][ln];
                s.x += v.x; s.y += v.y;
            }
            const int ikf = half * 16 + ik;
            const int b = bg * 8 + ((ln >> 4) & 1) * 4 + (ikf >> 3);
            const int h = hg * 8 + (ikf & 7);
            const int e = ec * 32 + (ln & 15) * 2;
            *(float2*)&g_embp[js][(b * NH + h) * NE + e] = s;
        }
    }
}

// ---------------------------------------------------------------------------
// Kernel 2 (PDL + tf32 MMA, hoisted split, K=128 two-stage, split-K=4):
// out[m][n] += sum_k emb[m][k]*w[n][k]  (bias already in out)
// M=256,N=512,K=512. Tiles 64m x 64n x 128k (two sequential 64-k stages
// reusing the uint2 planes) -> grid 128. Halves the epilogue REDG lanes
// (1.05M -> 0.52M: the largest exposed tail in the R16 accounting) and the
// per-block fixed costs; mainloop is R16's lean LDS.64+MMA (no cvt).
// ---------------------------------------------------------------------------
__global__ __launch_bounds__(256) void gemm_kernel(const float* __restrict__ w,
                                                   float* __restrict__ out) {
    const int t   = threadIdx.x;
    const int bid = blockIdx.x;        // 128 = 4 mt x 8 nt x 4 kt
    const int kt  = bid & 3;
    const int nt  = (bid >> 2) & 7;
    const int mt  = bid >> 5;
    const int m0 = mt * 64, n0 = nt * 64;

    extern __shared__ uint2 dsm[];     // 2 x 64 x 68 uint2 = 69632 B
    uint2 (*sa)[68] = (uint2(*)[68])dsm;             // A: [m][k] {hi,lo}
    uint2 (*sb)[68] = (uint2(*)[68])(dsm + 64 * 68); // B: [n][k] {hi,lo}

    const int wid  = t >> 5;
    const int lane = t & 31;
    const int gid  = lane >> 2;        // group id 0..7
    const int tig  = lane & 3;         // thread in group 0..3
    const int mw = (wid & 3) * 16;     // warp m-offset in tile
    const int nw = (wid >> 2) * 32;    // warp n-offset in tile

    float c[4][4];                     // [ntile][creg]
#pragma unroll
    for (int i = 0; i < 4; ++i)
#pragma unroll
        for (int j = 0; j < 4; ++j) c[i][j] = 0.f;

    bool gated = false;
#pragma unroll
    for (int kc = 0; kc < 2; ++kc) {
        const int k0 = kt * 128 + kc * 64;
        if (kc) __syncthreads();       // previous stage consumed before restaging

        // ---- B planes (stage 0 runs pre-gate: independent of emb) ---------
#pragma unroll
        for (int r = 0; r < 4; ++r) {
            const int lin = t + r * 256;        // 1024 float4 slots
            const int row = lin >> 4;           // n 0..63
            const int kq  = (lin & 15) * 4;     // 0..60
            const float4 b4 = *(const float4*)&w[(n0 + row) * NE + k0 + kq];
            sb[row][kq + 0] = tf32_split2(b4.x);
            sb[row][kq + 1] = tf32_split2(b4.y);
            sb[row][kq + 2] = tf32_split2(b4.z);
            sb[row][kq + 3] = tf32_split2(b4.w);
        }

        if (!gated) { cudaGridDependencySynchronize(); gated = true; }

        // ---- A planes: 64m x 64k, folded over the 4 j-split partials ------
#pragma unroll
        for (int r = 0; r < 4; ++r) {
            const int lin = t + r * 256;
            const int row = lin >> 4;           // m 0..63
            const int kq  = (lin & 15) * 4;
            const int aoff = (m0 + row) * NE + k0 + kq;
            float4 a = *(const float4*)&g_embp[0][aoff];
#pragma unroll
            for (int p = 1; p < JSPLIT; ++p) {
                const float4 v = *(const float4*)&g_embp[p][aoff];
                a.x += v.x; a.y += v.y; a.z += v.z; a.w += v.w;
            }
            sa[row][kq + 0] = tf32_split2(a.x);
            sa[row][kq + 1] = tf32_split2(a.y);
            sa[row][kq + 2] = tf32_split2(a.z);
            sa[row][kq + 3] = tf32_split2(a.w);
        }
        __syncthreads();

#pragma unroll
        for (int ks = 0; ks < 8; ++ks) {   // 8 mma k-steps of 8
            const int kb = ks * 8;
            const uint2 a0 = sa[mw + gid    ][kb + tig    ];
            const uint2 a1 = sa[mw + gid + 8][kb + tig    ];
            const uint2 a2 = sa[mw + gid    ][kb + tig + 4];
            const uint2 a3 = sa[mw + gid + 8][kb + tig + 4];
            const unsigned ah[4] = {a0.x, a1.x, a2.x, a3.x};
            const unsigned al[4] = {a0.y, a1.y, a2.y, a3.y};
#pragma unroll
            for (int ntile = 0; ntile < 4; ++ntile) {
                const uint2 b0 = sb[nw + ntile * 8 + gid][kb + tig    ];
                const uint2 b1 = sb[nw + ntile * 8 + gid][kb + tig + 4];
                const unsigned bh[2] = {b0.x, b1.x};
                const unsigned bl[2] = {b0.y, b1.y};
                mma_tf32(c[ntile], ah, bh);   // hi*hi
                mma_tf32(c[ntile], al, bh);   // lo*hi
                mma_tf32(c[ntile], ah, bl);   // hi*lo
            }
        }
    }

    // Epilogue: c0:(gid,2tig) c1:(gid,2tig+1) c2:(gid+8,2tig) c3:(gid+8,2tig+1)
    const int gm = m0 + mw + gid;
    const int gn = n0 + nw + tig * 2;
#pragma unroll
    for (int ntile = 0; ntile < 4; ++ntile) {
        float* op = &out[gm * NE + gn + ntile * 8];
        atomicAdd(op + 0,          c[ntile][0]);
        atomicAdd(op + 1,          c[ntile][1]);
        atomicAdd(op + 8 * NE + 0, c[ntile][2]);
        atomicAdd(op + 8 * NE + 1, c[ntile][3]);
    }
}

extern "C" void kernel_launch(void* const* d_in, const int* in_sizes, int n_in,
                              void* d_out, int out_size) {
    const float* x    = (const float*)d_in[0];  // [16,1,512,512]
    // d_in[1] = W_q, d_in[2] = W_k: mathematically dead (softmax cols sum to 1)
    const float* wv   = (const float*)d_in[3];  // [1,16,512,512]
    const float* mlpw = (const float*)d_in[4];  // [512,512]
    const float* mlpb = (const float*)d_in[5];  // [512]
    float* out = (float*)d_out;                 // [16,16,512]

    const int smem_bytes = 2 * 64 * 68 * (int)sizeof(uint2);  // 69632
    static int attr_set = 0;
    if (!attr_set) {   // idempotent host-side attribute (not a stream op)
        cudaFuncSetAttribute(gemm_kernel,
                             cudaFuncAttributeMaxDynamicSharedMemorySize, smem_bytes);
        attr_set = 1;
    }

    emb_kernel<<<256, 256>>>(x, wv, mlpb, out);

    cudaLaunchConfig_t cfg = {};
    cfg.gridDim  = dim3(128, 1, 1);
    cfg.blockDim = dim3(256, 1, 1);
    cfg.dynamicSmemBytes = smem_bytes;
    cudaLaunchAttribute attrs[1];
    attrs[0].id = cudaLaunchAttributeProgrammaticStreamSerialization;
    attrs[0].val.programmaticStreamSerializationAllowed = 1;
    cfg.attrs = attrs;
    cfg.numAttrs = 1;
    cudaLaunchKernelEx(&cfg, gemm_kernel, mlpw, (float*)d_out);
}